// round 4
// baseline (speedup 1.0000x reference)
#include <cuda_runtime.h>
#include <math.h>
#include <stdint.h>

// BuildingModule: 3-state RC thermal scan, B=8192 chains x 1023 serial steps.
// Warp-specialized blocks: warp0 = compute (1 thread per chain, 32 chains),
// warp1 = IO (cp.async staging of u, coalesced output drain).
// u staged gmem->smem (coalesced); outputs staged smem->gmem (coalesced).
// Math: incremental reciprocal (cubic poly for 2^-m), kl-prefolded coeffs.

#define BATCH   8192
#define TSTEPS  1024
#define CHUNK   16
#define NCHUNK  (TSTEPS / CHUNK)        // 64
#define ROWW    132                     // 128 data words + 4 pad (conflict-free)
#define OROWW   52                      // 48 data words + 4 pad
#define USTRIDE (TSTEPS * 8)            // floats per chain in u
#define OSTRIDE (TSTEPS * 3)            // floats per chain in out

__device__ __forceinline__ void cpa16(uint32_t s, const float* g) {
    asm volatile("cp.async.cg.shared.global [%0], [%1], 16;" :: "r"(s), "l"(g));
}
__device__ __forceinline__ void cpa_commit() {
    asm volatile("cp.async.commit_group;" ::: "memory");
}
__device__ __forceinline__ void cpa_wait1() {
    asm volatile("cp.async.wait_group 1;" ::: "memory");
}
__device__ __forceinline__ float rcpa(float x) {
    float y; asm("rcp.approx.ftz.f32 %0, %1;" : "=f"(y) : "f"(x)); return y;
}
__device__ __forceinline__ float ex2a(float x) {
    float y; asm("ex2.approx.ftz.f32 %0, %1;" : "=f"(y) : "f"(x)); return y;
}

__global__ void __launch_bounds__(64)
bm_kernel(const float* __restrict__ x0g,
          const float* __restrict__ ug,
          const float* __restrict__ lamg,
          float* __restrict__ outg)
{
    __shared__ float ub[2][32 * ROWW];    // u stage, double buffered (33792 B)
    __shared__ float ob[2][32 * OROWW];   // out stage, double buffered (13312 B)

    const int tid  = threadIdx.x;
    const int lane = tid & 31;
    const int wid  = tid >> 5;            // 0 = compute, 1 = IO
    const int b0   = blockIdx.x * 32;

    const float* up0 = ug + (size_t)b0 * USTRIDE;

    // ---- IO-warp staging macro: chunk C -> ub[BI]; lanes cover 512B/chain ----
#define STAGE(C, BI) do {                                                     \
    uint32_t s = (uint32_t)__cvta_generic_to_shared(&ub[BI][lane * 4]);       \
    const float* g = up0 + (size_t)(C) * (CHUNK * 8) + lane * 4;              \
    _Pragma("unroll")                                                         \
    for (int i_ = 0; i_ < 32; i_++) {                                         \
        cpa16(s, g);                                                          \
        s += ROWW * 4;                                                        \
        g += USTRIDE;                                                         \
    }                                                                         \
} while (0)

    // ---- compute-warp state ----
    float x0 = 0.f, x1 = 0.f, x2 = 0.f, i0 = 0.f, i1 = 0.f, i2 = 0.f;
    float g12_0 = 0.f, ng12_1 = 0.f, g23_1 = 0.f, ng23_2 = 0.f;
    float eeK0 = 0.f, eeK1 = 0.f, eeK2 = 0.f;
    float neeK0 = 0.f, neeK1 = 0.f, neeK2 = 0.f;
    float esK0 = 0.f, esK1 = 0.f, esK2 = 0.f;
    float ehK0 = 0.f, ehK1 = 0.f, ehK2 = 0.f;
    float ecK0 = 0.f, ecK1 = 0.f, ecK2 = 0.f;

    if (wid == 0) {
        const float e12 = expf(lamg[0]);
        const float e23 = expf(lamg[1]);
        const float ee0 = expf(lamg[2]),  ee1 = expf(lamg[3]),  ee2 = expf(lamg[4]);
        const float es0 = expf(lamg[5]),  es1 = expf(lamg[6]),  es2 = expf(lamg[7]);
        const float eh0 = expf(lamg[8]),  eh1 = expf(lamg[9]),  eh2 = expf(lamg[10]);
        const float ec0 = expf(lamg[11]), ec1 = expf(lamg[12]), ec2 = expf(lamg[13]);

        const float kl0 = (float)(60.0 / 10665991.0 * 1.4426950408889634);
        const float kl1 = (float)(60.0 / 27000000.0 * 1.4426950408889634);
        const float kl2 = (float)(60.0 /  7953253.0 * 1.4426950408889634);

        g12_0  =  kl0 * e12;   ng12_1 = -kl1 * e12;
        g23_1  =  kl1 * e23;   ng23_2 = -kl2 * e23;
        eeK0 = kl0*ee0; eeK1 = kl1*ee1; eeK2 = kl2*ee2;
        neeK0 = -eeK0;  neeK1 = -eeK1;  neeK2 = -eeK2;
        esK0 = kl0*es0; esK1 = kl1*es1; esK2 = kl2*es2;
        ehK0 = kl0*eh0; ehK1 = kl1*eh1; ehK2 = kl2*eh2;
        ecK0 = kl0*ec0; ecK1 = kl1*ec1; ecK2 = kl2*ec2;

        const int b = b0 + lane;
        x0 = x0g[b * 3 + 0];
        x1 = x0g[b * 3 + 1];
        x2 = x0g[b * 3 + 2];
        i0 = rcpa(x0); i1 = rcpa(x1); i2 = rcpa(x2);
        i0 = i0 * (2.0f - x0 * i0);
        i1 = i1 * (2.0f - x1 * i1);
        i2 = i2 * (2.0f - x2 * i2);
    } else {
        // IO warp: prime both u buffers.
        STAGE(0, 0); cpa_commit();
        STAGE(1, 1); cpa_commit();
        cpa_wait1();              // chunk 0 resident
    }

    __syncthreads();              // ub[0] visible to compute warp

    for (int c = 0; c < NCHUNK; c++) {
        const int bi = c & 1;

        if (wid == 0) {
            // ---------------- compute chunk c ----------------
            const float* row = &ub[bi][lane * ROWW];
            float* orow = &ob[bi][lane * OROWW];

            float4 ua = *(const float4*)(row);        // u0,u1,h0,h1
            float4 uc = *(const float4*)(row + 4);    // h2,c0,c1,c2

#pragma unroll
            for (int j = 0; j < CHUNK; j++) {
                float4 na, nc;
                if (j < CHUNK - 1) {
                    na = *(const float4*)(row + (j + 1) * 8);
                    nc = *(const float4*)(row + (j + 1) * 8 + 4);
                }

                // out row 16c+j <- current state, masked by u0 of this row
                {
                    const bool nm = (c == 0) && (j == 0);
                    const bool mv = !nm && (ua.x < 1e-6f);
                    orow[j * 3 + 0] = mv ? -1.0f : x0;
                    orow[j * 3 + 1] = mv ? -1.0f : x1;
                    orow[j * 3 + 2] = mv ? -1.0f : x2;
                }

                // scan step consuming this u row
                const float u0 = ua.x, u1 = ua.y;
                const float d12 = i0 - i1;
                const float d23 = i1 - i2;
                const float w0 = fmaf(esK0, u1, fmaf(ehK0, ua.z, fmaf(ecK0, uc.y, neeK0)));
                const float w1 = fmaf(esK1, u1, fmaf(ehK1, ua.w, fmaf(ecK1, uc.z, neeK1)));
                const float w2 = fmaf(esK2, u1, fmaf(ehK2, uc.x, fmaf(ecK2, uc.w, neeK2)));
                const float q0 = fmaf(eeK0, i0 * u0, w0);
                const float q1 = fmaf(eeK1, i1 * u0, w1);
                const float q2 = fmaf(eeK2, i2 * u0, w2);
                const float m0 = fmaf(g12_0  * d12, x1, q0);
                const float m1 = fmaf(g23_1  * d23, x2, fmaf(ng12_1 * d12, x0, q1));
                const float m2 = fmaf(ng23_2 * d23, x1, q2);
                // 2^-m cubic: literal coefficients (FFMA-imm form, rt 1)
                const float r0 = fmaf(fmaf(fmaf(-0.05550410866f, m0, 0.24022650696f), m0, -0.69314718056f), m0, 1.0f);
                const float r1 = fmaf(fmaf(fmaf(-0.05550410866f, m1, 0.24022650696f), m1, -0.69314718056f), m1, 1.0f);
                const float r2 = fmaf(fmaf(fmaf(-0.05550410866f, m2, 0.24022650696f), m2, -0.69314718056f), m2, 1.0f);
                x0 *= ex2a(m0);  x1 *= ex2a(m1);  x2 *= ex2a(m2);
                i0 *= r0;        i1 *= r1;        i2 *= r2;

                ua = na; uc = nc;
            }
        }

        __syncthreads();   // ob[bi] full; ub[bi] consumed

        if (wid == 1) {
            // ---------------- IO: drain ob[bi], stage chunk c+2 ----------------
#pragma unroll
            for (int it = 0; it < 12; it++) {
                const int unit  = it * 32 + lane;
                const int chain = unit / 12;
                const int o     = unit - chain * 12;
                const float4 v = *(const float4*)(&ob[bi][chain * OROWW + o * 4]);
                *(float4*)(outg + (size_t)(b0 + chain) * OSTRIDE
                           + (size_t)c * (CHUNK * 3) + o * 4) = v;
            }
            if (c + 2 < NCHUNK) STAGE(c + 2, bi);
            cpa_commit();          // uniform group count even when no cp.async
            cpa_wait1();           // chunk c+1 resident (c+2 may still fly)
        }

        __syncthreads();   // ub[(c+1)&1] staged+visible; ob[bi] free for c+2
    }
}

extern "C" void kernel_launch(void* const* d_in, const int* in_sizes, int n_in,
                              void* d_out, int out_size)
{
    const float* x0  = nullptr;
    const float* u   = nullptr;
    const float* lam = nullptr;
    for (int i = 0; i < n_in; i++) {
        if (in_sizes[i] == 14)               lam = (const float*)d_in[i];
        else if (in_sizes[i] == BATCH * 3)   x0  = (const float*)d_in[i];
        else                                 u   = (const float*)d_in[i];
    }
    bm_kernel<<<BATCH / 32, 64>>>(x0, u, lam, (float*)d_out);
}

// round 8
// speedup vs baseline: 1.0658x; 1.0658x over previous
#include <cuda_runtime.h>
#include <math.h>
#include <stdint.h>

// BuildingModule: 3-state RC thermal scan, B=8192 chains x 1023 serial steps.
// 64-thread blocks = 2 fully independent compute+IO warps (32 chains each),
// so the two warps land on different SMSPs (wid%4) and each gets its own
// issue port. No inter-warp sync. u staged gmem->smem via cp.async
// (coalesced); outputs staged smem->gmem (coalesced). Math: incremental
// reciprocal (cubic poly for 2^-m), kl-prefolded coefficients.

#define BATCH   8192
#define TSTEPS  1024
#define CHUNK   16
#define NCHUNK  (TSTEPS / CHUNK)        // 64
#define ROWW    132                     // 128 data words + 4 pad (conflict-free)
#define OROWW   52                      // 48 data words + 4 pad
#define USTRIDE (TSTEPS * 8)            // floats per chain in u
#define OSTRIDE (TSTEPS * 3)            // floats per chain in out

#define UB_WORDS   (2 * 32 * ROWW)      // per-warp u stage (double buffered)
#define OB_WORDS   (32 * OROWW)         // per-warp out stage
#define WARP_WORDS (UB_WORDS + OB_WORDS)
#define SMEM_BYTES (2 * WARP_WORDS * 4) // 80896 B per block

__device__ __forceinline__ void cpa16(uint32_t s, const float* g) {
    asm volatile("cp.async.cg.shared.global [%0], [%1], 16;" :: "r"(s), "l"(g));
}
__device__ __forceinline__ void cpa_commit() {
    asm volatile("cp.async.commit_group;" ::: "memory");
}
__device__ __forceinline__ void cpa_wait1() {
    asm volatile("cp.async.wait_group 1;" ::: "memory");
}
__device__ __forceinline__ void cpa_wait0() {
    asm volatile("cp.async.wait_group 0;" ::: "memory");
}
__device__ __forceinline__ float rcpa(float x) {
    float y; asm("rcp.approx.ftz.f32 %0, %1;" : "=f"(y) : "f"(x)); return y;
}
__device__ __forceinline__ float ex2a(float x) {
    float y; asm("ex2.approx.ftz.f32 %0, %1;" : "=f"(y) : "f"(x)); return y;
}

extern __shared__ float smem[];

__global__ void __launch_bounds__(64)
bm_kernel(const float* __restrict__ x0g,
          const float* __restrict__ ug,
          const float* __restrict__ lamg,
          float* __restrict__ outg)
{
    const int tid  = threadIdx.x;
    const int lane = tid & 31;
    const int wid  = tid >> 5;                 // 0 or 1 -> SMSP 0 / 1
    const int b0   = blockIdx.x * 64 + wid * 32;

    float* ub = smem + wid * WARP_WORDS;       // [2][32*ROWW]
    float* ob = ub + UB_WORDS;                 // [32*OROWW]

    const float e12 = expf(lamg[0]);
    const float e23 = expf(lamg[1]);
    const float ee0 = expf(lamg[2]),  ee1 = expf(lamg[3]),  ee2 = expf(lamg[4]);
    const float es0 = expf(lamg[5]),  es1 = expf(lamg[6]),  es2 = expf(lamg[7]);
    const float eh0 = expf(lamg[8]),  eh1 = expf(lamg[9]),  eh2 = expf(lamg[10]);
    const float ec0 = expf(lamg[11]), ec1 = expf(lamg[12]), ec2 = expf(lamg[13]);

    const float kl0 = (float)(60.0 / 10665991.0 * 1.4426950408889634);
    const float kl1 = (float)(60.0 / 27000000.0 * 1.4426950408889634);
    const float kl2 = (float)(60.0 /  7953253.0 * 1.4426950408889634);

    const float g12_0  =  kl0 * e12;
    const float ng12_1 = -kl1 * e12;
    const float g23_1  =  kl1 * e23;
    const float ng23_2 = -kl2 * e23;
    const float eeK0 = kl0*ee0, eeK1 = kl1*ee1, eeK2 = kl2*ee2;
    const float neeK0 = -eeK0, neeK1 = -eeK1, neeK2 = -eeK2;
    const float esK0 = kl0*es0, esK1 = kl1*es1, esK2 = kl2*es2;
    const float ehK0 = kl0*eh0, ehK1 = kl1*eh1, ehK2 = kl2*eh2;
    const float ecK0 = kl0*ec0, ecK1 = kl1*ec1, ecK2 = kl2*ec2;

    const int b = b0 + lane;
    float x0 = x0g[b * 3 + 0];
    float x1 = x0g[b * 3 + 1];
    float x2 = x0g[b * 3 + 2];
    float i0 = rcpa(x0), i1 = rcpa(x1), i2 = rcpa(x2);
    i0 = i0 * (2.0f - x0 * i0);
    i1 = i1 * (2.0f - x1 * i1);
    i2 = i2 * (2.0f - x2 * i2);

    const float* up0 = ug + (size_t)b0 * USTRIDE;   // warp's chain-0 u base

    // Stage chunk C into ub half BI: iteration i = chain i, lanes cover 512B.
#define STAGE(C, BI) do {                                                     \
    uint32_t s = (uint32_t)__cvta_generic_to_shared(                          \
                     &ub[(BI) * (32 * ROWW) + lane * 4]);                     \
    const float* g = up0 + (size_t)(C) * (CHUNK * 8) + lane * 4;              \
    _Pragma("unroll")                                                         \
    for (int i_ = 0; i_ < 32; i_++) {                                         \
        cpa16(s, g);                                                          \
        s += ROWW * 4;                                                        \
        g += USTRIDE;                                                         \
    }                                                                         \
    cpa_commit();                                                             \
} while (0)

    STAGE(0, 0);
    STAGE(1, 1);
    cpa_wait1();               // chunk 0 resident
    __syncwarp();

    for (int c = 0; c < NCHUNK; c++) {
        const int bi = c & 1;
        const float* row = &ub[bi * (32 * ROWW) + lane * ROWW];
        float* orow = &ob[lane * OROWW];

        // one-step-ahead register prefetch of the u row
        float4 ua = *(const float4*)(row);        // u0,u1,h0,h1
        float4 uc = *(const float4*)(row + 4);    // h2,c0,c1,c2

#pragma unroll
        for (int j = 0; j < CHUNK; j++) {
            float4 na, nc;
            if (j < CHUNK - 1) {
                na = *(const float4*)(row + (j + 1) * 8);
                nc = *(const float4*)(row + (j + 1) * 8 + 4);
            }

            // out row 16c+j <- current state, masked by u0 of this row
            {
                const bool nm = (c == 0) && (j == 0);
                const bool mv = !nm && (ua.x < 1e-6f);
                orow[j * 3 + 0] = mv ? -1.0f : x0;
                orow[j * 3 + 1] = mv ? -1.0f : x1;
                orow[j * 3 + 2] = mv ? -1.0f : x2;
            }

            // scan step consuming this u row
            const float u0 = ua.x, u1 = ua.y;
            const float d12 = i0 - i1;
            const float d23 = i1 - i2;
            const float w0 = fmaf(esK0, u1, fmaf(ehK0, ua.z, fmaf(ecK0, uc.y, neeK0)));
            const float w1 = fmaf(esK1, u1, fmaf(ehK1, ua.w, fmaf(ecK1, uc.z, neeK1)));
            const float w2 = fmaf(esK2, u1, fmaf(ehK2, uc.x, fmaf(ecK2, uc.w, neeK2)));
            const float q0 = fmaf(eeK0, i0 * u0, w0);
            const float q1 = fmaf(eeK1, i1 * u0, w1);
            const float q2 = fmaf(eeK2, i2 * u0, w2);
            const float m0 = fmaf(g12_0  * d12, x1, q0);
            const float m1 = fmaf(g23_1  * d23, x2, fmaf(ng12_1 * d12, x0, q1));
            const float m2 = fmaf(ng23_2 * d23, x1, q2);
            const float r0 = fmaf(fmaf(fmaf(-0.05550410866f, m0, 0.24022650696f), m0, -0.69314718056f), m0, 1.0f);
            const float r1 = fmaf(fmaf(fmaf(-0.05550410866f, m1, 0.24022650696f), m1, -0.69314718056f), m1, 1.0f);
            const float r2 = fmaf(fmaf(fmaf(-0.05550410866f, m2, 0.24022650696f), m2, -0.69314718056f), m2, 1.0f);
            x0 *= ex2a(m0);  x1 *= ex2a(m1);  x2 *= ex2a(m2);
            i0 *= r0;        i1 *= r1;        i2 *= r2;

            ua = na; uc = nc;
        }

        // prefetch chunk c+2 into the ub half just consumed
        if (c + 2 < NCHUNK) {
            STAGE(c + 2, bi);
        }

        __syncwarp();   // ob writes visible to all lanes

        // coalesced drain: 32 chains x 48 floats = 384 x 16B units, 12 iters
#pragma unroll
        for (int it = 0; it < 12; it++) {
            const int unit  = it * 32 + lane;
            const int chain = unit / 12;
            const int o     = unit - chain * 12;
            const float4 v = *(const float4*)(&ob[chain * OROWW + o * 4]);
            *(float4*)(outg + (size_t)(b0 + chain) * OSTRIDE
                       + (size_t)c * (CHUNK * 3) + o * 4) = v;
        }

        if (c + 2 < NCHUNK) cpa_wait1();   // chunk c+1 resident
        else                cpa_wait0();
        __syncwarp();   // staged data visible; ob safe to overwrite
    }
}

extern "C" void kernel_launch(void* const* d_in, const int* in_sizes, int n_in,
                              void* d_out, int out_size)
{
    const float* x0  = nullptr;
    const float* u   = nullptr;
    const float* lam = nullptr;
    for (int i = 0; i < n_in; i++) {
        if (in_sizes[i] == 14)               lam = (const float*)d_in[i];
        else if (in_sizes[i] == BATCH * 3)   x0  = (const float*)d_in[i];
        else                                 u   = (const float*)d_in[i];
    }
    cudaFuncSetAttribute(bm_kernel,
                         cudaFuncAttributeMaxDynamicSharedMemorySize,
                         SMEM_BYTES);
    bm_kernel<<<BATCH / 64, 64, SMEM_BYTES>>>(x0, u, lam, (float*)d_out);
}